// round 1
// baseline (speedup 1.0000x reference)
#include <cuda_runtime.h>
#include <cuda_bf16.h>

// Problem constants (fixed shapes for this problem)
#define TT   512
#define BN   8192
#define NTOT (TT * BN)        // 4,194,304
#define U    8                // pipeline depth (timesteps per chunk)
#define BLK  32
#define GRID (BN / BLK)       // 256 blocks

#define GAMMA_F 0.99f

// Per-block partial sums: [0..GRID) = actor, [GRID..2*GRID) = critic
__device__ float g_partial[2 * GRID];

// One thread owns one batch element b, scans t = T-1 .. 0 (backward).
// Key identities (RHO_THRESHOLD == C_THRESHOLD == 1):
//   ratio = p[a]*sum(ap) / (sum(p)*ap[a])       (no log/exp)
//   adv_t = min(ratio,1) * (r + gamma*(1-d)*carry - v)
//   vtrace_t = v_t + adv_t      -> carry
//   critic term = adv^2 ;  next_v only needed for the initial carry.
__global__ void __launch_bounds__(BLK)
vtrace_main(const float2* __restrict__ prob,
            const float2* __restrict__ aprob,
            const float*  __restrict__ v,
            const float*  __restrict__ nv,
            const float*  __restrict__ rew,
            const int*    __restrict__ act,
            const int*    __restrict__ dn)
{
    const int b = blockIdx.x * BLK + threadIdx.x;

    float carry  = __ldg(&nv[(TT - 1) * BN + b]);
    float actor  = 0.0f;
    float critic = 0.0f;

    // Register double buffer: 2 x U timesteps of raw inputs.
    float2 pB[2][U], apB[2][U];
    float  vB[2][U], rB[2][U];
    int    aB[2][U], dB[2][U];

    // Prime buffer 0 with steps T-1 .. T-U
    #pragma unroll
    for (int i = 0; i < U; i++) {
        const int idx = (TT - 1 - i) * BN + b;
        pB[0][i]  = __ldg(&prob[idx]);
        apB[0][i] = __ldg(&aprob[idx]);
        vB[0][i]  = __ldg(&v[idx]);
        rB[0][i]  = __ldg(&rew[idx]);
        aB[0][i]  = __ldg(&act[idx]);
        dB[0][i]  = __ldg(&dn[idx]);
    }

    int cur = 0;
    for (int thi = TT - 1; thi >= 0; thi -= U) {
        const int nxt = cur ^ 1;
        // Issue next chunk's loads BEFORE consuming the current buffer:
        // keeps ~48 independent LDGs in flight per thread while the
        // serial recurrence below executes.
        if (thi - U >= 0) {
            #pragma unroll
            for (int i = 0; i < U; i++) {
                const int idx = (thi - U - i) * BN + b;
                pB[nxt][i]  = __ldg(&prob[idx]);
                apB[nxt][i] = __ldg(&aprob[idx]);
                vB[nxt][i]  = __ldg(&v[idx]);
                rB[nxt][i]  = __ldg(&rew[idx]);
                aB[nxt][i]  = __ldg(&act[idx]);
                dB[nxt][i]  = __ldg(&dn[idx]);
            }
        }

        #pragma unroll
        for (int i = 0; i < U; i++) {
            const float2 p  = pB[cur][i];
            const float2 ap = apB[cur][i];
            const float  vv = vB[cur][i];
            const float  rr = rB[cur][i];
            const int    a  = aB[cur][i];
            const float  g  = dB[cur][i] ? 0.0f : GAMMA_F;

            const float pa    = a ? p.y  : p.x;
            const float apa   = a ? ap.y : ap.x;
            const float ratio = (pa * (ap.x + ap.y)) / ((p.x + p.y) * apa);
            const float rho   = fminf(ratio, 1.0f);

            const float adv = rho * (rr + g * carry - vv);
            carry  = vv + adv;                       // vtrace_t
            critic = fmaf(adv, adv, critic);         // (v - vtrace)^2 == adv^2

            const float cl = fminf(fmaxf(ratio, 1.0f - 0.2f), 1.0f + 0.2f);
            actor += fminf(ratio * adv, cl * adv);   // min(surr1, surr2)
        }
        cur = nxt;
    }

    // Deterministic warp reduction (block == 1 warp)
    #pragma unroll
    for (int o = 16; o > 0; o >>= 1) {
        actor  += __shfl_down_sync(0xffffffffu, actor,  o);
        critic += __shfl_down_sync(0xffffffffu, critic, o);
    }
    if (threadIdx.x == 0) {
        g_partial[blockIdx.x]        = actor;
        g_partial[GRID + blockIdx.x] = critic;
    }
}

// Single-block deterministic final reduction.
__global__ void vtrace_finish(float* __restrict__ out)
{
    __shared__ float sa[GRID];
    __shared__ float sc[GRID];
    const int t = threadIdx.x;
    sa[t] = g_partial[t];
    sc[t] = g_partial[GRID + t];
    __syncthreads();
    #pragma unroll
    for (int s = GRID / 2; s > 0; s >>= 1) {
        if (t < s) { sa[t] += sa[t + s]; sc[t] += sc[t + s]; }
        __syncthreads();
    }
    if (t == 0) {
        const float inv = 1.0f / (float)NTOT;
        // total = actor_loss + critic_loss
        //       = (-sum(min(surr)) + 0.5*sum(adv^2)) / N
        out[0] = (-sa[0] + 0.5f * sc[0]) * inv;
    }
}

extern "C" void kernel_launch(void* const* d_in, const int* in_sizes, int n_in,
                              void* d_out, int out_size)
{
    const float2* prob  = (const float2*)d_in[0];  // [T,B,2] f32 -> float2 [T,B]
    const float2* aprob = (const float2*)d_in[1];  // [T,B,2] f32
    const float*  v     = (const float*)d_in[2];   // [T,B]
    const float*  nv    = (const float*)d_in[3];   // [T,B]
    const float*  rew   = (const float*)d_in[4];   // [T,B]
    const int*    act   = (const int*)d_in[5];     // [T,B] int32
    const int*    dn    = (const int*)d_in[6];     // [T,B] int32

    float* out = (float*)d_out;

    vtrace_main<<<GRID, BLK>>>(prob, aprob, v, nv, rew, act, dn);
    vtrace_finish<<<1, GRID>>>(out);
}

// round 2
// speedup vs baseline: 3.0585x; 3.0585x over previous
#include <cuda_runtime.h>
#include <cuda_bf16.h>

#define TT    512
#define BN    8192
#define NTOT  (TT * BN)         // 4,194,304
#define PAIRS (BN / 2)          // 4096 (2 batch elems per thread)
#define NC    32                // time chunks
#define S     (TT / NC)         // 16 steps per chunk
#define BLK   256
#define BPC   (PAIRS / BLK)     // 16 blocks per chunk
#define G13   (NC * BPC)        // 512 blocks for pass1/pass3

#define GAMMA_F 0.99f

// Scratch (device globals: allocation-free)
__device__ float g_ratio[NTOT];      // 16 MB: per-element importance ratio
__device__ float g_Ac[NC * BN];      // per-(chunk,b) affine A
__device__ float g_Bc[NC * BN];      // per-(chunk,b) affine B
__device__ float g_entry[NC * BN];   // carry entering each chunk (at its end boundary)
__device__ float g_part[2 * G13];    // per-block partials: [0..G13) actor, rest critic

// ---------------------------------------------------------------------------
// Pass 1: compute ratio per element; compose chunk affine map (A, B).
//   carry_t = A_t * carry_{t+1} + B_t,  A_t = rho*g,  B_t = v + rho*(r - v)
// Thread = (chunk c, batch pair). Fully coalesced float4/float2/int2 loads.
// ---------------------------------------------------------------------------
__global__ void __launch_bounds__(BLK)
pass1(const float4* __restrict__ prob,   // [T, B/2] pairs of (p0,p1)
      const float4* __restrict__ aprob,
      const float2* __restrict__ v,
      const float2* __restrict__ rew,
      const int2*   __restrict__ act,
      const int2*   __restrict__ dn)
{
    const int c    = blockIdx.x >> 4;                       // chunk
    const int pair = ((blockIdx.x & 15) << 8) + threadIdx.x;
    const int t1   = c * S + S - 1;

    float Ax = 1.0f, Ay = 1.0f, Bx = 0.0f, By = 0.0f;

    #pragma unroll
    for (int i = 0; i < S; i++) {
        const int t    = t1 - i;                 // descend: compose F <- step_t o F
        const int pidx = t * PAIRS + pair;

        const float4 p  = __ldg(&prob[pidx]);
        const float4 ap = __ldg(&aprob[pidx]);
        const float2 vv = __ldg(&v[pidx]);
        const float2 rr = __ldg(&rew[pidx]);
        const int2   aa = __ldg(&act[pidx]);
        const int2   dd = __ldg(&dn[pidx]);

        // lane 0 (batch elem 2*pair)
        const float pa0   = aa.x ? p.y  : p.x;
        const float apa0  = aa.x ? ap.y : ap.x;
        const float rat0  = __fdividef(pa0 * (ap.x + ap.y), (p.x + p.y) * apa0);
        const float g0    = dd.x ? 0.0f : GAMMA_F;
        const float rho0  = fminf(rat0, 1.0f);
        const float At0   = rho0 * g0;
        const float Bt0   = fmaf(rho0, rr.x - vv.x, vv.x);
        Ax = At0 * Ax;
        Bx = fmaf(At0, Bx, Bt0);

        // lane 1 (batch elem 2*pair+1)
        const float pa1   = aa.y ? p.w  : p.z;
        const float apa1  = aa.y ? ap.w : ap.z;
        const float rat1  = __fdividef(pa1 * (ap.z + ap.w), (p.z + p.w) * apa1);
        const float g1    = dd.y ? 0.0f : GAMMA_F;
        const float rho1  = fminf(rat1, 1.0f);
        const float At1   = rho1 * g1;
        const float Bt1   = fmaf(rho1, rr.y - vv.y, vv.y);
        Ay = At1 * Ay;
        By = fmaf(At1, By, Bt1);

        reinterpret_cast<float2*>(g_ratio)[pidx] = make_float2(rat0, rat1);
    }

    const int cidx = c * PAIRS + pair;
    reinterpret_cast<float2*>(g_Ac)[cidx] = make_float2(Ax, Ay);
    reinterpret_cast<float2*>(g_Bc)[cidx] = make_float2(Bx, By);
}

// ---------------------------------------------------------------------------
// Pass 2: serial combine over NC chunks per batch element.
//   entry[NC-1] = next_v[T-1];  entry[c-1] = A[c]*entry[c] + B[c]
// ---------------------------------------------------------------------------
__global__ void __launch_bounds__(BLK)
pass2(const float* __restrict__ nv)
{
    const int b = blockIdx.x * BLK + threadIdx.x;   // 0..BN
    float e = __ldg(&nv[(TT - 1) * BN + b]);
    g_entry[(NC - 1) * BN + b] = e;
    #pragma unroll
    for (int c = NC - 1; c >= 1; c--) {
        e = fmaf(g_Ac[c * BN + b], e, g_Bc[c * BN + b]);
        g_entry[(c - 1) * BN + b] = e;
    }
}

// ---------------------------------------------------------------------------
// Pass 3: replay recurrence per chunk from known entry carry; accumulate
// actor / critic partial sums. Reads only ratio, v, r, done (16 B/elem).
// ---------------------------------------------------------------------------
__global__ void __launch_bounds__(BLK)
pass3(const float2* __restrict__ v,
      const float2* __restrict__ rew,
      const int2*   __restrict__ dn)
{
    const int c    = blockIdx.x >> 4;
    const int pair = ((blockIdx.x & 15) << 8) + threadIdx.x;
    const int t1   = c * S + S - 1;

    float2 carry = reinterpret_cast<const float2*>(g_entry)[c * PAIRS + pair];
    float actor = 0.0f, critic = 0.0f;

    #pragma unroll
    for (int i = 0; i < S; i++) {
        const int t    = t1 - i;
        const int pidx = t * PAIRS + pair;

        const float2 ra = reinterpret_cast<const float2*>(g_ratio)[pidx];
        const float2 vv = __ldg(&v[pidx]);
        const float2 rr = __ldg(&rew[pidx]);
        const int2   dd = __ldg(&dn[pidx]);

        // lane 0
        {
            const float g   = dd.x ? 0.0f : GAMMA_F;
            const float rho = fminf(ra.x, 1.0f);
            const float adv = rho * (rr.x + g * carry.x - vv.x);
            critic = fmaf(adv, adv, critic);
            const float cl = fminf(fmaxf(ra.x, 0.8f), 1.2f);
            actor += fminf(ra.x * adv, cl * adv);
            carry.x = vv.x + adv;
        }
        // lane 1
        {
            const float g   = dd.y ? 0.0f : GAMMA_F;
            const float rho = fminf(ra.y, 1.0f);
            const float adv = rho * (rr.y + g * carry.y - vv.y);
            critic = fmaf(adv, adv, critic);
            const float cl = fminf(fmaxf(ra.y, 0.8f), 1.2f);
            actor += fminf(ra.y * adv, cl * adv);
            carry.y = vv.y + adv;
        }
    }

    // Deterministic block reduction (8 warps)
    __shared__ float sa[8], sc[8];
    #pragma unroll
    for (int o = 16; o > 0; o >>= 1) {
        actor  += __shfl_down_sync(0xffffffffu, actor,  o);
        critic += __shfl_down_sync(0xffffffffu, critic, o);
    }
    const int w = threadIdx.x >> 5;
    if ((threadIdx.x & 31) == 0) { sa[w] = actor; sc[w] = critic; }
    __syncthreads();
    if (threadIdx.x == 0) {
        float A = 0.0f, C = 0.0f;
        #pragma unroll
        for (int k = 0; k < 8; k++) { A += sa[k]; C += sc[k]; }
        g_part[blockIdx.x]       = A;
        g_part[G13 + blockIdx.x] = C;
    }
}

// ---------------------------------------------------------------------------
// Final reduction over 512 block partials.
// ---------------------------------------------------------------------------
__global__ void __launch_bounds__(512)
finish(float* __restrict__ out)
{
    __shared__ float sa[512], sc[512];
    const int t = threadIdx.x;
    sa[t] = g_part[t];
    sc[t] = g_part[G13 + t];
    __syncthreads();
    #pragma unroll
    for (int s = 256; s > 0; s >>= 1) {
        if (t < s) { sa[t] += sa[t + s]; sc[t] += sc[t + s]; }
        __syncthreads();
    }
    if (t == 0) {
        const float inv = 1.0f / (float)NTOT;
        out[0] = (-sa[0] + 0.5f * sc[0]) * inv;   // actor_loss + critic_loss
    }
}

extern "C" void kernel_launch(void* const* d_in, const int* in_sizes, int n_in,
                              void* d_out, int out_size)
{
    const float4* prob  = (const float4*)d_in[0];
    const float4* aprob = (const float4*)d_in[1];
    const float2* v     = (const float2*)d_in[2];
    const float*  nv    = (const float*)d_in[3];
    const float2* rew   = (const float2*)d_in[4];
    const int2*   act   = (const int2*)d_in[5];
    const int2*   dn    = (const int2*)d_in[6];
    float* out = (float*)d_out;

    pass1<<<G13, BLK>>>(prob, aprob, v, rew, act, dn);
    pass2<<<BN / BLK, BLK>>>(nv);
    pass3<<<G13, BLK>>>(v, rew, dn);
    finish<<<1, 512>>>(out);
}

// round 3
// speedup vs baseline: 4.7395x; 1.5496x over previous
#include <cuda_runtime.h>
#include <cuda_bf16.h>

#define TT    512
#define BN    8192
#define NTOT  (TT * BN)         // 4,194,304
#define PAIRS (BN / 2)          // 4096
#define NC    32                // time chunks
#define S     (TT / NC)         // 16 steps per chunk
#define BLK   256
#define BPC   (PAIRS / BLK)     // 16 blocks per chunk
#define G13   (NC * BPC)        // 512 blocks

#define GAMMA_F 0.99f

// Scratch (device globals: allocation-free)
__device__ float g_ratio[NTOT];          // packed: |ratio| with done bit in sign
__device__ float g_Ac[NC * BN];          // chunk affine A (layout: [c][pair] as float2)
__device__ float g_Bc[NC * BN];          // chunk affine B
__device__ float g_part[2 * G13];        // block partials: actor | critic
__device__ unsigned int g_ctr;           // pass3 completion counter

// ---------------------------------------------------------------------------
// Pass 1: per-element ratio (done packed in sign bit) + chunk affine (A,B).
//   carry_t = A_t*carry_{t+1} + B_t ;  A_t = rho*g ,  B_t = v + rho*(r - v)
// Streaming inputs (prob/aprob/act/dn) use __ldcs (evict-first) so that
// ratio + v + rew stay L2-resident for pass3.
// ---------------------------------------------------------------------------
__global__ void __launch_bounds__(BLK)
pass1(const float4* __restrict__ prob,
      const float4* __restrict__ aprob,
      const float2* __restrict__ v,
      const float2* __restrict__ rew,
      const int2*   __restrict__ act,
      const int2*   __restrict__ dn)
{
    if (blockIdx.x == 0 && threadIdx.x == 0) g_ctr = 0;  // reset for pass3

    const int c    = blockIdx.x >> 4;
    const int pair = ((blockIdx.x & 15) << 8) + threadIdx.x;
    const int t1   = c * S + S - 1;

    float Ax = 1.0f, Ay = 1.0f, Bx = 0.0f, By = 0.0f;

    #pragma unroll
    for (int i = 0; i < S; i++) {
        const int t    = t1 - i;
        const int pidx = t * PAIRS + pair;

        const float4 p  = __ldcs(&prob[pidx]);
        const float4 ap = __ldcs(&aprob[pidx]);
        const int2   aa = __ldcs(&act[pidx]);
        const int2   dd = __ldcs(&dn[pidx]);
        const float2 vv = __ldg(&v[pidx]);
        const float2 rr = __ldg(&rew[pidx]);

        // lane 0
        const float pa0  = aa.x ? p.y  : p.x;
        const float apa0 = aa.x ? ap.y : ap.x;
        const float rat0 = __fdividef(pa0 * (ap.x + ap.y), (p.x + p.y) * apa0);
        const float g0   = dd.x ? 0.0f : GAMMA_F;
        const float rho0 = fminf(rat0, 1.0f);
        const float At0  = rho0 * g0;
        const float Bt0  = fmaf(rho0, rr.x - vv.x, vv.x);
        Ax = At0 * Ax;
        Bx = fmaf(At0, Bx, Bt0);

        // lane 1
        const float pa1  = aa.y ? p.w  : p.z;
        const float apa1 = aa.y ? ap.w : ap.z;
        const float rat1 = __fdividef(pa1 * (ap.z + ap.w), (p.z + p.w) * apa1);
        const float g1   = dd.y ? 0.0f : GAMMA_F;
        const float rho1 = fminf(rat1, 1.0f);
        const float At1  = rho1 * g1;
        const float Bt1  = fmaf(rho1, rr.y - vv.y, vv.y);
        Ay = At1 * Ay;
        By = fmaf(At1, By, Bt1);

        // pack done bit into sign of ratio (ratio >= 0 always)
        const unsigned u0 = __float_as_uint(rat0) | ((unsigned)dd.x << 31);
        const unsigned u1 = __float_as_uint(rat1) | ((unsigned)dd.y << 31);
        reinterpret_cast<float2*>(g_ratio)[pidx] =
            make_float2(__uint_as_float(u0), __uint_as_float(u1));
    }

    const int cidx = c * PAIRS + pair;
    reinterpret_cast<float2*>(g_Ac)[cidx] = make_float2(Ax, Ay);
    reinterpret_cast<float2*>(g_Bc)[cidx] = make_float2(Bx, By);
}

// ---------------------------------------------------------------------------
// Pass 3 (fused pass2 + finish):
//   prologue: compose entry carry for this chunk from A/B arrays (L2-hot)
//   body:     replay recurrence, accumulate actor/critic
//   epilogue: block reduce; last block does the final deterministic reduction
// ---------------------------------------------------------------------------
__global__ void __launch_bounds__(BLK)
pass3(const float2* __restrict__ v,
      const float2* __restrict__ rew,
      const float*  __restrict__ nv,
      float*        __restrict__ out)
{
    const int c    = blockIdx.x >> 4;
    const int pair = ((blockIdx.x & 15) << 8) + threadIdx.x;
    const int t1   = c * S + S - 1;

    // ---- prologue: entry carry (compose chunks NC-1 .. c+1, right-to-left)
    const int b0 = 2 * pair;
    float2 carry = make_float2(__ldg(&nv[(TT - 1) * BN + b0]),
                               __ldg(&nv[(TT - 1) * BN + b0 + 1]));
    for (int cc = NC - 1; cc > c; cc--) {
        const float2 A = reinterpret_cast<const float2*>(g_Ac)[cc * PAIRS + pair];
        const float2 B = reinterpret_cast<const float2*>(g_Bc)[cc * PAIRS + pair];
        carry.x = fmaf(A.x, carry.x, B.x);
        carry.y = fmaf(A.y, carry.y, B.y);
    }

    // ---- body
    float actor = 0.0f, critic = 0.0f;

    #pragma unroll
    for (int i = 0; i < S; i++) {
        const int t    = t1 - i;
        const int pidx = t * PAIRS + pair;

        const float2 rp = reinterpret_cast<const float2*>(g_ratio)[pidx];
        const float2 vv = __ldg(&v[pidx]);
        const float2 rr = __ldg(&rew[pidx]);

        // lane 0
        {
            const unsigned u = __float_as_uint(rp.x);
            const float ratio = __uint_as_float(u & 0x7fffffffu);
            const float g    = (u >> 31) ? 0.0f : GAMMA_F;
            const float rho  = fminf(ratio, 1.0f);
            const float adv  = rho * (rr.x + g * carry.x - vv.x);
            critic = fmaf(adv, adv, critic);
            const float cl = fminf(fmaxf(ratio, 0.8f), 1.2f);
            actor += fminf(ratio * adv, cl * adv);
            carry.x = vv.x + adv;
        }
        // lane 1
        {
            const unsigned u = __float_as_uint(rp.y);
            const float ratio = __uint_as_float(u & 0x7fffffffu);
            const float g    = (u >> 31) ? 0.0f : GAMMA_F;
            const float rho  = fminf(ratio, 1.0f);
            const float adv  = rho * (rr.y + g * carry.y - vv.y);
            critic = fmaf(adv, adv, critic);
            const float cl = fminf(fmaxf(ratio, 0.8f), 1.2f);
            actor += fminf(ratio * adv, cl * adv);
            carry.y = vv.y + adv;
        }
    }

    // ---- block reduction (deterministic)
    __shared__ float sa[8], sc[8];
    #pragma unroll
    for (int o = 16; o > 0; o >>= 1) {
        actor  += __shfl_down_sync(0xffffffffu, actor,  o);
        critic += __shfl_down_sync(0xffffffffu, critic, o);
    }
    const int w = threadIdx.x >> 5;
    if ((threadIdx.x & 31) == 0) { sa[w] = actor; sc[w] = critic; }
    __syncthreads();
    if (threadIdx.x == 0) {
        float A = 0.0f, C = 0.0f;
        #pragma unroll
        for (int k = 0; k < 8; k++) { A += sa[k]; C += sc[k]; }
        g_part[blockIdx.x]       = A;
        g_part[G13 + blockIdx.x] = C;
    }

    // ---- last-block final reduction (fixed order -> deterministic)
    __shared__ bool is_last;
    if (threadIdx.x == 0) {
        __threadfence();
        const unsigned n = atomicAdd(&g_ctr, 1u);
        is_last = (n == (unsigned)(G13 - 1));
    }
    __syncthreads();
    if (is_last) {
        const int t = threadIdx.x;
        __shared__ float ra[BLK], rc[BLK];
        ra[t] = g_part[t] + g_part[t + BLK];
        rc[t] = g_part[G13 + t] + g_part[G13 + t + BLK];
        __syncthreads();
        #pragma unroll
        for (int s = BLK / 2; s > 0; s >>= 1) {
            if (t < s) { ra[t] += ra[t + s]; rc[t] += rc[t + s]; }
            __syncthreads();
        }
        if (t == 0) {
            const float inv = 1.0f / (float)NTOT;
            out[0] = (-ra[0] + 0.5f * rc[0]) * inv;  // actor + critic loss
        }
    }
}

extern "C" void kernel_launch(void* const* d_in, const int* in_sizes, int n_in,
                              void* d_out, int out_size)
{
    const float4* prob  = (const float4*)d_in[0];
    const float4* aprob = (const float4*)d_in[1];
    const float2* v     = (const float2*)d_in[2];
    const float*  nv    = (const float*)d_in[3];
    const float2* rew   = (const float2*)d_in[4];
    const int2*   act   = (const int2*)d_in[5];
    const int2*   dn    = (const int2*)d_in[6];
    float* out = (float*)d_out;

    pass1<<<G13, BLK>>>(prob, aprob, v, rew, act, dn);
    pass3<<<G13, BLK>>>(v, rew, nv, out);
}